// round 17
// baseline (speedup 1.0000x reference)
#include <cuda_runtime.h>
#include <cuda_fp16.h>
#include <cstdint>

#define B_   8
#define HWN  4096
#define C3   768
#define CATT 512

// half intermediates (dw/attention corridor)
__device__ __half g_qkvh[B_ * C3 * HWN];
__device__ __half g_pwh [B_ * C3 * HWN];     // only q channels of each head written
__device__ float  g_kvp[B_ * 64][20][72];    // h<32: chunks 0..3 ; h>=32: 4..19

// fp16 split planes (GEMM operands)
__device__ __half g_xh [B_ * 256 * HWN];
__device__ __half g_xl [B_ * 256 * HWN];
__device__ __half g_ath[B_ * CATT * HWN];
__device__ __half g_atl[B_ * CATT * HWN];
__device__ __half g_wqh[768 * 256];
__device__ __half g_wql[768 * 256];
__device__ __half g_wph[256 * 512];
__device__ __half g_wpl[256 * 512];

// ===========================================================================
// helpers
// ===========================================================================
__device__ __forceinline__ uint32_t smem_u32(const void* p) {
    uint32_t a;
    asm("{ .reg .u64 t; cvta.to.shared.u64 t, %1; cvt.u32.u64 %0, t; }"
        : "=r"(a) : "l"(p));
    return a;
}
__device__ __forceinline__ void cpa16(uint32_t dst, const void* src) {
    asm volatile("cp.async.cg.shared.global [%0], [%1], 16;"
                 :: "r"(dst), "l"(src) : "memory");
}
#define CP_COMMIT() asm volatile("cp.async.commit_group;" ::: "memory")
#define CP_WAIT1()  asm volatile("cp.async.wait_group 1;" ::: "memory")

#define LDSM(r0,r1,r2,r3,a) \
    asm volatile("ldmatrix.sync.aligned.m8n8.x4.shared.b16 {%0,%1,%2,%3}, [%4];" \
        : "=r"(r0),"=r"(r1),"=r"(r2),"=r"(r3) : "r"(a))
#define LDSMT(r0,r1,r2,r3,a) \
    asm volatile("ldmatrix.sync.aligned.m8n8.x4.trans.shared.b16 {%0,%1,%2,%3}, [%4];" \
        : "=r"(r0),"=r"(r1),"=r"(r2),"=r"(r3) : "r"(a))
#define MMA(acc_, a_, b0_, b1_) \
    asm volatile("mma.sync.aligned.m16n8k16.row.col.f32.f16.f16.f32 " \
        "{%0,%1,%2,%3}, {%4,%5,%6,%7}, {%8,%9}, {%0,%1,%2,%3};" \
        : "+f"(acc_[0]), "+f"(acc_[1]), "+f"(acc_[2]), "+f"(acc_[3]) \
        : "r"(a_[0]), "r"(a_[1]), "r"(a_[2]), "r"(a_[3]), "r"(b0_), "r"(b1_))

__device__ __forceinline__ float4 ldh4(const __half* p) {
    uint2 u = *reinterpret_cast<const uint2*>(p);
    __half2 a = *reinterpret_cast<__half2*>(&u.x);
    __half2 b = *reinterpret_cast<__half2*>(&u.y);
    float2 fa = __half22float2(a), fb = __half22float2(b);
    return make_float4(fa.x, fa.y, fb.x, fb.y);
}
__device__ __forceinline__ void sth4(__half* p, float4 v) {
    uint2 u;
    __half2 a = __floats2half2_rn(v.x, v.y);
    __half2 b = __floats2half2_rn(v.z, v.w);
    u.x = *reinterpret_cast<uint32_t*>(&a);
    u.y = *reinterpret_cast<uint32_t*>(&b);
    *reinterpret_cast<uint2*>(p) = u;
}

// ===========================================================================
// merged split: fp32 -> fp16 hi/lo planes for x, w_qkv, w_proj.
// ===========================================================================
#define NX4 ((B_ * 256 * HWN) / 4)
#define NQ4 ((768 * 256) / 4)
#define NP4 ((256 * 512) / 4)

__device__ __forceinline__ void split4(const float* __restrict__ src,
                                       __half2* __restrict__ h2,
                                       __half2* __restrict__ l2, int i)
{
    float4 v = reinterpret_cast<const float4*>(src)[i];
    float f[4] = {v.x, v.y, v.z, v.w};
    __half hh[4], ll[4];
#pragma unroll
    for (int j = 0; j < 4; j++) {
        hh[j] = __float2half_rn(f[j]);
        ll[j] = __float2half_rn(f[j] - __half2float(hh[j]));
    }
    h2[2 * i]     = __halves2half2(hh[0], hh[1]);
    h2[2 * i + 1] = __halves2half2(hh[2], hh[3]);
    l2[2 * i]     = __halves2half2(ll[0], ll[1]);
    l2[2 * i + 1] = __halves2half2(ll[2], ll[3]);
}

__global__ __launch_bounds__(256) void split_all_k(
    const float* __restrict__ x, const float* __restrict__ wq,
    const float* __restrict__ wp,
    __half2* xh, __half2* xl, __half2* qh, __half2* ql,
    __half2* ph, __half2* pl)
{
    int i = blockIdx.x * 256 + threadIdx.x;
    if (i < NX4)                   split4(x,  xh, xl, i);
    else if (i < NX4 + NQ4)        split4(wq, qh, ql, i - NX4);
    else if (i < NX4 + NQ4 + NP4)  split4(wp, ph, pl, i - NX4 - NQ4);
}

// ===========================================================================
// fp16x2-split GEMM, K-tile 32, templated M-tile; WH: write __half output.
// (R12/R15 proven config)
// ===========================================================================
template<int MT, bool WH>
__global__ __launch_bounds__(256, 2) void gemm_fp16x2(
    const __half* __restrict__ Ah, const __half* __restrict__ Al,
    const __half* __restrict__ Bh, const __half* __restrict__ Bl,
    void* __restrict__ Csrc, int M, int N, int K,
    const float* __restrict__ gamma, const float* __restrict__ beta,
    const float* __restrict__ mean,  const float* __restrict__ var)
{
    constexpr int RT    = MT * 32;
    constexpr int APL   = RT * 64;
    constexpr int AOFFL = APL;
    constexpr int BOFFH = 2 * APL;
    constexpr int BOFFL = 2 * APL + 8704;
    constexpr int STGB  = 2 * APL + 2 * 8704;

    extern __shared__ char dsm[];
    const uint32_t sb = smem_u32(dsm);

    const int tid = threadIdx.x, lane = tid & 31, warp = tid >> 5;
    const int wm = warp >> 2, wn = warp & 3;
    const int gr = lane >> 2, gc = lane & 3;

    const size_t bz = (size_t)blockIdx.z * K * N;

    const __half* aBaseH = Ah + (size_t)(blockIdx.y * RT) * K;
    const __half* aBaseL = Al + (size_t)(blockIdx.y * RT) * K;
    const __half* bSrcH = Bh + bz + blockIdx.x * 128;
    const __half* bSrcL = Bl + bz + blockIdx.x * 128;

    auto issue = [&](int kt) {
        uint32_t st = sb + (kt % 3) * STGB;
        int kbase = kt * 32;
        for (int c = tid; c < RT * 4; c += 256) {
            int row = c >> 2, seg = c & 3;
            uint32_t ad = st + row * 64 + ((seg ^ ((row >> 1) & 3)) * 16);
            const size_t so = (size_t)row * K + kbase + seg * 8;
            cpa16(ad,         aBaseH + so);
            cpa16(ad + AOFFL, aBaseL + so);
        }
#pragma unroll
        for (int j = 0; j < 2; j++) {
            int q = tid * 2 + j;
            int krow = q >> 4, seg = q & 15;
            uint32_t bd = st + krow * 272 + seg * 16;
            const size_t so = (size_t)(kbase + krow) * N + seg * 8;
            cpa16(bd + BOFFH, bSrcH + so);
            cpa16(bd + BOFFL, bSrcL + so);
        }
    };

    float acc[MT][4][4];
#pragma unroll
    for (int mt = 0; mt < MT; mt++)
#pragma unroll
        for (int nt = 0; nt < 4; nt++)
#pragma unroll
            for (int i = 0; i < 4; i++) acc[mt][nt][i] = 0.f;

    const int nk = K / 32;
    issue(0); CP_COMMIT();
    issue(1); CP_COMMIT();

    const uint32_t brow = (lane & 7) + 8 * ((lane >> 3) & 1);
    const uint32_t bn   = 8 * (lane >> 4);
    const int arl = lane & 15;
    const int ach = lane >> 4;

    for (int kt = 0; kt < nk; kt++) {
        CP_WAIT1();
        __syncthreads();
        if (kt + 2 < nk) issue(kt + 2);
        CP_COMMIT();

        const uint32_t st = sb + (kt % 3) * STGB;

#pragma unroll
        for (int ks = 0; ks < 2; ks++) {
            uint32_t bfr[2][2][4];
#pragma unroll
            for (int ng = 0; ng < 2; ng++) {
                uint32_t ad = st + BOFFH + (ks * 16 + brow) * 272
                            + (wn * 32 + ng * 16 + bn) * 2;
                LDSMT(bfr[0][ng][0], bfr[0][ng][1], bfr[0][ng][2], bfr[0][ng][3], ad);
                LDSMT(bfr[1][ng][0], bfr[1][ng][1], bfr[1][ng][2], bfr[1][ng][3],
                      ad + (BOFFL - BOFFH));
            }
#pragma unroll
            for (int mt = 0; mt < MT; mt++) {
                int rA = wm * (MT * 16) + mt * 16 + arl;
                int c = ks * 2 + ach;
                uint32_t ma = st + rA * 64 + ((c ^ ((rA >> 1) & 3)) * 16);
                uint32_t ah[4], al[4];
                LDSM(ah[0], ah[1], ah[2], ah[3], ma);
                LDSM(al[0], al[1], al[2], al[3], ma + AOFFL);
#pragma unroll
                for (int nt = 0; nt < 4; nt++)
                    MMA(acc[mt][nt], ah, bfr[1][nt >> 1][2 * (nt & 1)],
                        bfr[1][nt >> 1][2 * (nt & 1) + 1]);
#pragma unroll
                for (int nt = 0; nt < 4; nt++)
                    MMA(acc[mt][nt], al, bfr[0][nt >> 1][2 * (nt & 1)],
                        bfr[0][nt >> 1][2 * (nt & 1) + 1]);
#pragma unroll
                for (int nt = 0; nt < 4; nt++)
                    MMA(acc[mt][nt], ah, bfr[0][nt >> 1][2 * (nt & 1)],
                        bfr[0][nt >> 1][2 * (nt & 1) + 1]);
            }
        }
    }

    // epilogue
#pragma unroll
    for (int mt = 0; mt < MT; mt++) {
        int r0 = blockIdx.y * RT + wm * (MT * 16) + mt * 16 + gr;
        int r1 = r0 + 8;
        float sc0 = 1.f, bi0 = 0.f, sc1 = 1.f, bi1 = 0.f;
        if (gamma) {
            float i0 = gamma[r0] * rsqrtf(var[r0] + 1e-5f);
            float i1 = gamma[r1] * rsqrtf(var[r1] + 1e-5f);
            sc0 = i0; bi0 = beta[r0] - mean[r0] * i0;
            sc1 = i1; bi1 = beta[r1] - mean[r1] * i1;
        }
#pragma unroll
        for (int nt = 0; nt < 4; nt++) {
            int col = blockIdx.x * 128 + wn * 32 + nt * 8 + gc * 2;
            float v00 = acc[mt][nt][0] * sc0 + bi0, v01 = acc[mt][nt][1] * sc0 + bi0;
            float v10 = acc[mt][nt][2] * sc1 + bi1, v11 = acc[mt][nt][3] * sc1 + bi1;
            if (WH) {
                __half* Cm = (__half*)Csrc + (size_t)blockIdx.z * M * N;
                *reinterpret_cast<__half2*>(Cm + (size_t)r0 * N + col) =
                    __floats2half2_rn(v00, v01);
                *reinterpret_cast<__half2*>(Cm + (size_t)r1 * N + col) =
                    __floats2half2_rn(v10, v11);
            } else {
                float* Cm = (float*)Csrc + (size_t)blockIdx.z * M * N;
                *reinterpret_cast<float2*>(Cm + (size_t)r0 * N + col) =
                    make_float2(v00, v01);
                *reinterpret_cast<float2*>(Cm + (size_t)r1 * N + col) =
                    make_float2(v10, v11);
            }
        }
    }
}

// ===========================================================================
// Fused per-head depthwise 5x5 + grouped pw + kv accumulation.
// Block = one head (24 ch) x 16x16 px tile, 128 threads (2 px each).
// Writes ONLY the q channels to g_pwh; k,v reduced into g_kvp[bh][4+tile].
// dynamic smem: t[24][20][24] floats (46080 B) overlaid with red[128][73].
// NOTE: needs cudaFuncSetAttribute (static 3.1KB + dynamic 46080 > 48KB default).
// ===========================================================================
#define DWATT_SMEM 46080

__global__ __launch_bounds__(128) void dwatt_k(const float* __restrict__ w_dw,
                                               const float* __restrict__ w_pw)
{
    const int tile = blockIdx.x, hh = blockIdx.y, b = blockIdx.z;
    const int x0 = (tile & 3) * 16, y0 = (tile >> 2) * 16;
    const int tid = threadIdx.x;

    extern __shared__ char dsm[];
    float* t   = (float*)dsm;          // [24][20][24]
    float* red = (float*)dsm;          // [128][73] overlay (after sync)
    __shared__ float wd[24][25];
    __shared__ float wp[192];

    const __half* ip = g_qkvh + ((size_t)b * C3 + hh * 24) * HWN;

    for (int i = tid; i < 600; i += 128) wd[i / 25][i % 25] = w_dw[hh * 600 + i];
    for (int i = tid; i < 192; i += 128) wp[i] = w_pw[hh * 192 + i];

    // load 24ch x 20y x 24x halo (cols gx = x0-4 .. x0+19), 4-half chunks
    for (int i = tid; i < 2880; i += 128) {
        int ch = i / 120, rem = i % 120;
        int yy = rem / 6, c4 = rem % 6;
        int gy = y0 + yy - 2, gx = x0 + c4 * 4 - 4;
        float4 v = make_float4(0.f, 0.f, 0.f, 0.f);
        if ((unsigned)gy < 64u && (unsigned)gx <= 60u)
            v = ldh4(ip + ch * HWN + gy * 64 + gx);
        *reinterpret_cast<float4*>(&t[ch * 480 + yy * 24 + c4 * 4]) = v;
    }
    __syncthreads();

    float acc[72];
#pragma unroll
    for (int i = 0; i < 72; i++) acc[i] = 0.f;

    const int px = tid & 15, py0 = tid >> 4;

#pragma unroll
    for (int pp = 0; pp < 2; pp++) {
        const int py = py0 + pp * 8;

        auto dwconv = [&](int ch) {
            float s = 0.f;
            const float* base = &t[ch * 480 + py * 24 + px + 2];
#pragma unroll
            for (int ky = 0; ky < 5; ky++)
#pragma unroll
                for (int kx = 0; kx < 5; kx++)
                    s += base[ky * 24 + kx] * wd[ch][ky * 5 + kx];
            return s;
        };

        float dwv[8];
        // group 0 -> q (store)
#pragma unroll
        for (int ch = 0; ch < 8; ch++) dwv[ch] = dwconv(ch);
        {
            __half* op = g_pwh + ((size_t)b * C3 + hh * 24) * HWN
                       + (y0 + py) * 64 + x0 + px;
#pragma unroll
            for (int o = 0; o < 8; o++) {
                float s = 0.f;
#pragma unroll
                for (int i = 0; i < 8; i++) s += wp[o * 8 + i] * dwv[i];
                op[o * HWN] = __float2half_rn(s);
            }
        }
        // group 1 -> k
        float kk[8];
#pragma unroll
        for (int ch = 0; ch < 8; ch++) dwv[ch] = dwconv(8 + ch);
#pragma unroll
        for (int o = 0; o < 8; o++) {
            float s = 0.f;
#pragma unroll
            for (int i = 0; i < 8; i++) s += wp[64 + o * 8 + i] * dwv[i];
            kk[o] = fmaxf(s, 0.f);
        }
        // group 2 -> v
        float vv[8];
#pragma unroll
        for (int ch = 0; ch < 8; ch++) dwv[ch] = dwconv(16 + ch);
#pragma unroll
        for (int o = 0; o < 8; o++) {
            float s = 0.f;
#pragma unroll
            for (int i = 0; i < 8; i++) s += wp[128 + o * 8 + i] * dwv[i];
            vv[o] = s;
        }
        // kv outer product
#pragma unroll
        for (int d = 0; d < 8; d++) {
#pragma unroll
            for (int e = 0; e < 8; e++) acc[d * 9 + e] += kk[d] * vv[e];
            acc[d * 9 + 8] += kk[d];
        }
    }

    // transpose reduce (red overlays t; all t reads are done)
    __syncthreads();
#pragma unroll
    for (int i = 0; i < 72; i++) red[tid * 73 + i] = acc[i];
    __syncthreads();
    if (tid < 72) {
        float s = 0.f;
#pragma unroll 16
        for (int t2 = 0; t2 < 128; t2++) s += red[t2 * 73 + tid];
        g_kvp[b * 64 + 32 + hh][4 + tile][tid] = s;
    }
}

// ===========================================================================
// Attention pass 1 (qkv heads 0..31 only): R15 structure, half inputs.
// ===========================================================================
__global__ __launch_bounds__(128) void att1_k()
{
    const int h = blockIdx.x & 31, b = blockIdx.x >> 5;
    const int bh = b * 64 + h;

    const __half* src = g_qkvh + ((size_t)b * C3 + h * 24) * HWN;

    float acc[72];
#pragma unroll
    for (int i = 0; i < 72; i++) acc[i] = 0.f;

#pragma unroll
    for (int it = 0; it < 2; it++) {
        const int hw = blockIdx.y * 1024 + it * 512 + threadIdx.x * 4;
        float4 kk[8], vv[8];
#pragma unroll
        for (int d = 0; d < 8; d++) {
            float4 v = ldh4(src + (8 + d) * HWN + hw);
            kk[d] = make_float4(fmaxf(v.x, 0.f), fmaxf(v.y, 0.f),
                                fmaxf(v.z, 0.f), fmaxf(v.w, 0.f));
        }
#pragma unroll
        for (int e = 0; e < 8; e++)
            vv[e] = ldh4(src + (16 + e) * HWN + hw);

#pragma unroll
        for (int d = 0; d < 8; d++) {
#pragma unroll
            for (int e = 0; e < 8; e++)
                acc[d * 9 + e] += kk[d].x * vv[e].x + kk[d].y * vv[e].y
                                + kk[d].z * vv[e].z + kk[d].w * vv[e].w;
            acc[d * 9 + 8] += kk[d].x + kk[d].y + kk[d].z + kk[d].w;
        }
    }

    __shared__ float red[128][73];
#pragma unroll
    for (int i = 0; i < 72; i++) red[threadIdx.x][i] = acc[i];
    __syncthreads();
    if (threadIdx.x < 72) {
        float s = 0.f;
#pragma unroll 16
        for (int t = 0; t < 128; t++) s += red[t][threadIdx.x];
        g_kvp[bh][blockIdx.y][threadIdx.x] = s;
    }
}

// ===========================================================================
// Attention pass 2: out = relu(q) @ kv, normalize; fp16 hi/lo planes out.
// h<32: kv = sum chunks 0..3 ; h>=32: sum chunks 4..19.
// ===========================================================================
__global__ __launch_bounds__(128) void att2_k()
{
    const int bh = blockIdx.x;
    const int h = bh & 63, b = bh >> 6;

    const __half* src = (h < 32)
        ? g_qkvh + ((size_t)b * C3 + h * 24) * HWN
        : g_pwh  + ((size_t)b * C3 + (h - 32) * 24) * HWN;

    __shared__ float kvm[72];
    if (threadIdx.x < 72) {
        float s = 0.f;
        if (h < 32) {
#pragma unroll
            for (int c = 0; c < 4; c++) s += g_kvp[bh][c][threadIdx.x];
        } else {
#pragma unroll
            for (int c = 4; c < 20; c++) s += g_kvp[bh][c][threadIdx.x];
        }
        kvm[threadIdx.x] = s;
    }
    __syncthreads();

    const size_t dbase = ((size_t)b * CATT + h * 8) * HWN;
    const int hw = blockIdx.y * 512 + threadIdx.x * 4;

    float4 q[8];
#pragma unroll
    for (int d = 0; d < 8; d++) {
        float4 v = ldh4(src + d * HWN + hw);
        q[d] = make_float4(fmaxf(v.x, 0.f), fmaxf(v.y, 0.f),
                           fmaxf(v.z, 0.f), fmaxf(v.w, 0.f));
    }
    float4 den = make_float4(0.f, 0.f, 0.f, 0.f);
#pragma unroll
    for (int d = 0; d < 8; d++) {
        float w = kvm[d * 9 + 8];
        den.x += q[d].x * w; den.y += q[d].y * w;
        den.z += q[d].z * w; den.w += q[d].w * w;
    }
    float4 inv;
    inv.x = 1.f / (den.x + 1e-15f); inv.y = 1.f / (den.y + 1e-15f);
    inv.z = 1.f / (den.z + 1e-15f); inv.w = 1.f / (den.w + 1e-15f);

#pragma unroll
    for (int e = 0; e < 8; e++) {
        float4 o = make_float4(0.f, 0.f, 0.f, 0.f);
#pragma unroll
        for (int d = 0; d < 8; d++) {
            float w = kvm[d * 9 + e];
            o.x += q[d].x * w; o.y += q[d].y * w;
            o.z += q[d].z * w; o.w += q[d].w * w;
        }
        float val[4] = {o.x * inv.x, o.y * inv.y, o.z * inv.z, o.w * inv.w};
        __half hh[4], ll[4];
#pragma unroll
        for (int j = 0; j < 4; j++) {
            hh[j] = __float2half_rn(val[j]);
            ll[j] = __float2half_rn(val[j] - __half2float(hh[j]));
        }
        __half2* ph = reinterpret_cast<__half2*>(&g_ath[dbase + e * HWN + hw]);
        __half2* pl = reinterpret_cast<__half2*>(&g_atl[dbase + e * HWN + hw]);
        ph[0] = __halves2half2(hh[0], hh[1]);
        ph[1] = __halves2half2(hh[2], hh[3]);
        pl[0] = __halves2half2(ll[0], ll[1]);
        pl[1] = __halves2half2(ll[2], ll[3]);
    }
}

// ===========================================================================
extern "C" void kernel_launch(void* const* d_in, const int* in_sizes, int n_in,
                              void* d_out, int out_size)
{
    const float* x      = (const float*)d_in[0];
    const float* w_qkv  = (const float*)d_in[1];
    const float* w_dw   = (const float*)d_in[2];
    const float* w_pw   = (const float*)d_in[3];
    const float* w_proj = (const float*)d_in[4];
    const float* gm     = (const float*)d_in[5];
    const float* bt     = (const float*)d_in[6];
    const float* mn     = (const float*)d_in[7];
    const float* vr     = (const float*)d_in[8];
    float* out = (float*)d_out;

    __half *xh, *xl, *ath, *atl, *wqh, *wql, *wph, *wpl, *qkvh;
    cudaGetSymbolAddress((void**)&qkvh, g_qkvh);
    cudaGetSymbolAddress((void**)&xh,  g_xh);
    cudaGetSymbolAddress((void**)&xl,  g_xl);
    cudaGetSymbolAddress((void**)&ath, g_ath);
    cudaGetSymbolAddress((void**)&atl, g_atl);
    cudaGetSymbolAddress((void**)&wqh, g_wqh);
    cudaGetSymbolAddress((void**)&wql, g_wql);
    cudaGetSymbolAddress((void**)&wph, g_wph);
    cudaGetSymbolAddress((void**)&wpl, g_wpl);

    cudaFuncSetAttribute(gemm_fp16x2<3, true>,
                         cudaFuncAttributeMaxDynamicSharedMemorySize, 89088);
    cudaFuncSetAttribute(gemm_fp16x2<4, false>,
                         cudaFuncAttributeMaxDynamicSharedMemorySize, 101376);
    cudaFuncSetAttribute(dwatt_k,
                         cudaFuncAttributeMaxDynamicSharedMemorySize, DWATT_SMEM);

    // 0) merged split (x, w_qkv, w_proj)
    int total4 = NX4 + NQ4 + NP4;
    split_all_k<<<(total4 + 255) / 256, 256>>>(
        x, w_qkv, w_proj,
        (__half2*)xh, (__half2*)xl, (__half2*)wqh, (__half2*)wql,
        (__half2*)wph, (__half2*)wpl);

    // 1) qkv GEMM [TM=96], half output
    gemm_fp16x2<3, true><<<dim3(32, 8, B_), 256, 89088>>>(
        wqh, wql, xh, xl, qkvh, 768, HWN, 256, nullptr, nullptr, nullptr, nullptr);
    // 2) fused dw + pw + kv-accumulate (pw heads)
    dwatt_k<<<dim3(16, 32, B_), 128, DWATT_SMEM>>>(w_dw, w_pw);
    // 3) attention pass 1 (qkv heads only)
    att1_k<<<dim3(B_ * 32, 4), 128>>>();
    // 4) attention pass 2 (all heads)
    att2_k<<<dim3(B_ * 64, 8), 128>>>();
    // 5) proj + BN [TM=128], fp32 output
    gemm_fp16x2<4, false><<<dim3(32, 2, B_), 256, 101376>>>(
        wph, wpl, ath, atl, out, 256, HWN, 512, gm, bt, mn, vr);
}